// round 1
// baseline (speedup 1.0000x reference)
#include <cuda_runtime.h>
#include <math.h>

#define BATCH 128
#define NKPT  80
#define NSX   40
#define BK    32

// Scratch (device globals -- no allocation allowed)
__device__ float g_h0[BATCH * NKPT * 256];
__device__ float g_h1[BATCH * NKPT * 256];
__device__ float g_PA[NKPT * BATCH * 256];
__device__ float g_PB[NKPT * BATCH * 256];
__device__ float g_PD[NKPT * BATCH * 256];
__device__ float g_PT[NKPT * BATCH * 256];

// Tiled fp32 GEMM body: C[128 x 64tile] += X[128 x K] * W[O x K]^T
// X row stride ldx, W row stride ldw. 256 threads, 8x4 per-thread tile.
__device__ __forceinline__ void gemm_body(
    const float* __restrict__ Xb, int ldx,
    const float* __restrict__ Wb, int ldw,
    int K, int O, int nBase0,
    float (&acc)[8][4],
    float (*Xs)[BK + 1], float (*Ws)[BK + 1])
{
    const int tid   = threadIdx.x;
    const int mBase = (tid & 15) * 8;
    const int nSub  = (tid >> 4) * 4;

#pragma unroll
    for (int i = 0; i < 8; ++i)
#pragma unroll
        for (int jj = 0; jj < 4; ++jj) acc[i][jj] = 0.f;

    for (int k0 = 0; k0 < K; k0 += BK) {
        // load X tile: 128 x BK  (4096 floats / 256 threads = 16 each)
#pragma unroll
        for (int i = tid; i < 128 * BK; i += 256) {
            int r = i >> 5;       // / BK
            int c = i & (BK - 1); // % BK
            Xs[r][c] = Xb[(size_t)r * ldx + k0 + c];
        }
        // load W tile: 64 x BK (guarded on O)
#pragma unroll
        for (int i = tid; i < 64 * BK; i += 256) {
            int r = i >> 5;
            int c = i & (BK - 1);
            int o = nBase0 + r;
            Ws[r][c] = (o < O) ? Wb[(size_t)o * ldw + k0 + c] : 0.f;
        }
        __syncthreads();
#pragma unroll
        for (int kk = 0; kk < BK; ++kk) {
            float a[8], b[4];
#pragma unroll
            for (int i = 0; i < 8; ++i) a[i] = Xs[mBase + i][kk];
#pragma unroll
            for (int jj = 0; jj < 4; ++jj) b[jj] = Ws[nSub + jj][kk];
#pragma unroll
            for (int i = 0; i < 8; ++i)
#pragma unroll
                for (int jj = 0; jj < 4; ++jj) acc[i][jj] += a[i] * b[jj];
        }
        __syncthreads();
    }
}

// ---------------------------------------------------------------------------
// Stage 0: h0[b][j] = sum_k x[b][k] * W0[j][k] + b0[j];  j in [0, 20480)
// grid: 320 blocks of 64 output cols each.
__global__ void k_gemm0(const float* __restrict__ X, const float* __restrict__ W,
                        const float* __restrict__ bias)
{
    __shared__ float Xs[128][BK + 1];
    __shared__ float Ws[64][BK + 1];
    float acc[8][4];
    const int nBase0 = blockIdx.x * 64;
    gemm_body(X, 1024, W, 1024, 1024, 20480, nBase0, acc, Xs, Ws);

    const int tid   = threadIdx.x;
    const int mBase = (tid & 15) * 8;
    const int nSub  = (tid >> 4) * 4;
#pragma unroll
    for (int i = 0; i < 8; ++i)
#pragma unroll
        for (int jj = 0; jj < 4; ++jj) {
            int o = nBase0 + nSub + jj;
            g_h0[(size_t)(mBase + i) * 20480 + o] = acc[i][jj] + bias[o];
        }
}

// ---------------------------------------------------------------------------
// Projection: for node m (0..79), projection type p (0..3), output
//   P_p[m][b][o] = sum_c h[b][m][c] * W[o][l_p(m)*C + c]
// l_p: p=0 (A): j+1   p=1 (B): j   p=2 (D): 0   p=3 (T): 40   (j = m % 40)
// grid: (ceil(O/64), 4, 80)
__global__ void k_proj(int ssel, const float* __restrict__ W, int C, int O)
{
    __shared__ float Xs[128][BK + 1];
    __shared__ float Ws[64][BK + 1];
    const float* h = ssel ? g_h1 : g_h0;

    const int m    = blockIdx.z;
    const int p    = blockIdx.y;
    const int jloc = m % NSX;
    const int l    = (p == 0) ? (jloc + 1) : (p == 1) ? jloc : (p == 2) ? 0 : 40;
    float* out     = (p == 0) ? g_PA : (p == 1) ? g_PB : (p == 2) ? g_PD : g_PT;

    const int nBase0 = blockIdx.x * 64;
    float acc[8][4];
    gemm_body(h + (size_t)m * C, NKPT * C,
              W + (size_t)l * C, 41 * C,
              C, O, nBase0, acc, Xs, Ws);

    const int tid   = threadIdx.x;
    const int mBase = (tid & 15) * 8;
    const int nSub  = (tid >> 4) * 4;
#pragma unroll
    for (int i = 0; i < 8; ++i)
#pragma unroll
        for (int jj = 0; jj < 4; ++jj) {
            int o = nBase0 + nSub + jj;
            if (o < O)
                out[((size_t)m * BATCH + (mBase + i)) * O + o] = acc[i][jj];
        }
}

// ---------------------------------------------------------------------------
// Combine: out[b][f*40+ii][o] =
//   bias[o] + D[f40+ii] + prefix_{j<ii} A[f40+j] + suffix_{j>ii} B[f40+j]
//          + T[(1-f)*40+ii]
// suffix = totalB - inclusive-prefixB (exact at ii=39).
// One thread per (b, f, o).
__global__ void k_combine(const float* __restrict__ bias, int O, int apply_elu,
                          int dsel, float* __restrict__ outp)
{
    float* out = (dsel == 0) ? g_h0 : (dsel == 1) ? g_h1 : outp;

    int t = blockIdx.x * blockDim.x + threadIdx.x;
    int total = BATCH * 2 * O;
    if (t >= total) return;
    int o = t % O;
    int f = (t / O) & 1;
    int b = t / (2 * O);
    int base = f * NSX;

    float totB = 0.f;
    for (int j = 0; j < NSX; ++j)
        totB += g_PB[((size_t)(base + j) * BATCH + b) * O + o];

    float accA = 0.f, accBinc = 0.f;
    const float bv = bias[o];
    for (int ii = 0; ii < NSX; ++ii) {
        int m = base + ii;
        size_t idx = ((size_t)m * BATCH + b) * O + o;
        accBinc += g_PB[idx];
        int mo = (1 - f) * NSX + ii;  // time partner
        float v = bv + g_PD[idx]
                + g_PT[((size_t)mo * BATCH + b) * O + o]
                + accA + (totB - accBinc);
        if (apply_elu) v = (v > 0.f) ? v : expm1f(v);
        out[((size_t)b * NKPT + m) * O + o] = v;
        accA += g_PA[idx];
    }
}

// ---------------------------------------------------------------------------
extern "C" void kernel_launch(void* const* d_in, const int* in_sizes, int n_in,
                              void* d_out, int out_size)
{
    const float* x  = (const float*)d_in[0];
    const float* W0 = (const float*)d_in[1];
    const float* b0 = (const float*)d_in[2];
    const float* W1 = (const float*)d_in[3];
    const float* b1 = (const float*)d_in[4];
    const float* W2 = (const float*)d_in[5];
    const float* b2 = (const float*)d_in[6];
    const float* W3 = (const float*)d_in[7];
    const float* b3 = (const float*)d_in[8];
    const float* W4 = (const float*)d_in[9];
    const float* b4 = (const float*)d_in[10];
    // d_in[11] = indices: structure is deterministic and hardcoded above.

    // Stage 0: x @ W0^T + b0 -> g_h0 [128][80][256]
    k_gemm0<<<320, 256>>>(x, W0, b0);

    // Layer 1: C=256 -> O=256, ELU, g_h0 -> g_h1
    k_proj<<<dim3(4, 4, 80), 256>>>(0, W1, 256, 256);
    k_combine<<<(BATCH * 2 * 256 + 255) / 256, 256>>>(b1, 256, 1, 1, nullptr);

    // Layer 2: C=256 -> O=128, ELU, g_h1 -> g_h0
    k_proj<<<dim3(2, 4, 80), 256>>>(1, W2, 256, 128);
    k_combine<<<(BATCH * 2 * 128 + 255) / 256, 256>>>(b2, 128, 1, 0, nullptr);

    // Layer 3: C=128 -> O=64, ELU, g_h0 -> g_h1
    k_proj<<<dim3(1, 4, 80), 256>>>(0, W3, 128, 64);
    k_combine<<<(BATCH * 2 * 64 + 255) / 256, 256>>>(b3, 64, 1, 1, nullptr);

    // Layer 4: C=64 -> O=2, no ELU, g_h1 -> d_out
    k_proj<<<dim3(1, 4, 80), 256>>>(1, W4, 64, 2);
    k_combine<<<(BATCH * 2 * 2 + 255) / 256, 256>>>(b4, 2, 0, 2, (float*)d_out);
}

// round 3
// speedup vs baseline: 1.0236x; 1.0236x over previous
#include <cuda_runtime.h>
#include <math.h>

#define BATCH 128
#define NKPT  80
#define NSX   40

// Scratch (device globals -- no allocation allowed)
__device__ float g_h0[BATCH * NKPT * 256];
__device__ float g_h1[BATCH * NKPT * 256];
__device__ float g_PA[NKPT * BATCH * 256];
__device__ float g_PB[NKPT * BATCH * 256];
__device__ float g_PD[NKPT * BATCH * 256];
__device__ float g_PT[NKPT * BATCH * 256];

// ---------------------------------------------------------------------------
// GEMM core: C[128 x NT] = X[128 x K] * W[O x K]^T  (NT = 16*TN)
// k-major shared tiles, float4 global loads, float4 smem fragment loads.
// 256 threads; per-thread 8 rows x TN cols.
template<int TN, int BKT, int K>
__device__ __forceinline__ void gemm_core(
    const float* __restrict__ Xb, int ldx,
    const float* __restrict__ Wb, int ldw,
    int O, int nBase0,
    float (&acc)[8][TN], float* Xs, float* Ws)
{
    constexpr int NT = 16 * TN;
    const int tid   = threadIdx.x;
    const int mBase = (tid & 15) * 8;
    const int nOff  = (tid >> 4) * TN;

#pragma unroll
    for (int i = 0; i < 8; ++i)
#pragma unroll
        for (int j = 0; j < TN; ++j) acc[i][j] = 0.f;

#pragma unroll 1
    for (int k0 = 0; k0 < K; k0 += BKT) {
        // X tile: 128 rows x BKT k (float4 along k, scatter k-major)
        constexpr int XF4 = 128 * BKT / 4;
        constexpr int KQ  = BKT / 4;
#pragma unroll
        for (int i = tid; i < XF4; i += 256) {
            int r  = i / KQ;
            int cq = i % KQ;
            float4 v = *reinterpret_cast<const float4*>(Xb + (size_t)r * ldx + k0 + cq * 4);
            Xs[(cq * 4 + 0) * 128 + r] = v.x;
            Xs[(cq * 4 + 1) * 128 + r] = v.y;
            Xs[(cq * 4 + 2) * 128 + r] = v.z;
            Xs[(cq * 4 + 3) * 128 + r] = v.w;
        }
        // W tile: NT rows x BKT k
        constexpr int WF4 = NT * BKT / 4;
#pragma unroll
        for (int i = tid; i < WF4; i += 256) {
            int r  = i / KQ;
            int cq = i % KQ;
            int o  = nBase0 + r;
            float4 v = make_float4(0.f, 0.f, 0.f, 0.f);
            if (o < O)
                v = *reinterpret_cast<const float4*>(Wb + (size_t)o * ldw + k0 + cq * 4);
            Ws[(cq * 4 + 0) * NT + r] = v.x;
            Ws[(cq * 4 + 1) * NT + r] = v.y;
            Ws[(cq * 4 + 2) * NT + r] = v.z;
            Ws[(cq * 4 + 3) * NT + r] = v.w;
        }
        __syncthreads();
#pragma unroll
        for (int kk = 0; kk < BKT; ++kk) {
            float a[8], b[TN];
            float4 a0 = *reinterpret_cast<const float4*>(Xs + kk * 128 + mBase);
            float4 a1 = *reinterpret_cast<const float4*>(Xs + kk * 128 + mBase + 4);
            a[0]=a0.x; a[1]=a0.y; a[2]=a0.z; a[3]=a0.w;
            a[4]=a1.x; a[5]=a1.y; a[6]=a1.z; a[7]=a1.w;
#pragma unroll
            for (int j = 0; j < TN; j += 4) {
                float4 bv = *reinterpret_cast<const float4*>(Ws + kk * NT + nOff + j);
                b[j]=bv.x; b[j+1]=bv.y; b[j+2]=bv.z; b[j+3]=bv.w;
            }
#pragma unroll
            for (int i = 0; i < 8; ++i)
#pragma unroll
                for (int j = 0; j < TN; ++j) acc[i][j] += a[i] * b[j];
        }
        __syncthreads();
    }
}

// ---------------------------------------------------------------------------
// Stage 0: h0[b][j] = x[b] . W0[j] + b0[j],  j in [0,20480). 160 blocks x 128 cols.
__global__ __launch_bounds__(256, 2)
void k_gemm0(const float* __restrict__ X, const float* __restrict__ W,
             const float* __restrict__ bias)
{
    __shared__ float Xs[32 * 128];
    __shared__ float Ws[32 * 128];
    float acc[8][8];
    const int nBase0 = blockIdx.x * 128;
    gemm_core<8, 32, 1024>(X, 1024, W, 1024, 20480, nBase0, acc, Xs, Ws);

    const int tid   = threadIdx.x;
    const int mBase = (tid & 15) * 8;
    const int nOff  = (tid >> 4) * 8;
#pragma unroll
    for (int i = 0; i < 8; ++i)
#pragma unroll
        for (int j = 0; j < 8; j += 4) {
            int o = nBase0 + nOff + j;
            float4 v;
            v.x = acc[i][j+0] + bias[o+0];
            v.y = acc[i][j+1] + bias[o+1];
            v.z = acc[i][j+2] + bias[o+2];
            v.w = acc[i][j+3] + bias[o+3];
            *reinterpret_cast<float4*>(&g_h0[(size_t)(mBase + i) * 20480 + o]) = v;
        }
}

// ---------------------------------------------------------------------------
// Projection: P_p[m][b][o] = sum_c h[b][m][c] * W[o][l_p(m)*C + c]
// l_p: p=0 (A): j+1   p=1 (B): j   p=2 (D): 0   p=3 (T): 40   (j = m % 40)
// grid: (O/(16*TN), 4, 80)
template<int TN, int BKT, int C, int O>
__global__ __launch_bounds__(256, 2)
void k_proj(int ssel, const float* __restrict__ W)
{
    __shared__ float Xs[BKT * 128];
    __shared__ float Ws[BKT * 16 * TN];
    const float* h = ssel ? g_h1 : g_h0;

    const int m    = blockIdx.z;
    const int p    = blockIdx.y;
    const int jloc = m % NSX;
    const int l    = (p == 0) ? (jloc + 1) : (p == 1) ? jloc : (p == 2) ? 0 : 40;
    float* out     = (p == 0) ? g_PA : (p == 1) ? g_PB : (p == 2) ? g_PD : g_PT;

    const int nBase0 = blockIdx.x * (16 * TN);
    float acc[8][TN];
    gemm_core<TN, BKT, C>(h + (size_t)m * C, NKPT * C,
                          W + (size_t)l * C, 41 * C,
                          O, nBase0, acc, Xs, Ws);

    const int tid   = threadIdx.x;
    const int mBase = (tid & 15) * 8;
    const int nOff  = (tid >> 4) * TN;
#pragma unroll
    for (int i = 0; i < 8; ++i)
#pragma unroll
        for (int j = 0; j < TN; j += 4) {
            int o = nBase0 + nOff + j;
            if (o < O) {
                float4 v = make_float4(acc[i][j], acc[i][j+1], acc[i][j+2], acc[i][j+3]);
                *reinterpret_cast<float4*>(
                    &out[((size_t)m * BATCH + (mBase + i)) * O + o]) = v;
            }
        }
}

// ---------------------------------------------------------------------------
// Layer 4 projection: C=64, O=2. One block per node m; all 4 p's share X in smem.
// 256 threads = exactly one (b, o) pair per thread (128 batches x 2 outputs).
__global__ __launch_bounds__(256)
void k_proj4(const float* __restrict__ W)
{
    __shared__ float Xsm[128 * 65];     // padded: bank-conflict-free by b
    __shared__ float Wsm[4][2][65];
    const int m    = blockIdx.x;
    const int jloc = m % NSX;
    const int tid  = threadIdx.x;
    const float* h = g_h1;              // layer-3 output lives in g_h1 (C=64)

    // X: 128 x 64 (layout [b][80][64])
#pragma unroll
    for (int i = tid; i < 128 * 16; i += 256) {
        int r  = i >> 4;
        int cq = i & 15;
        float4 v = *reinterpret_cast<const float4*>(h + ((size_t)r * NKPT + m) * 64 + cq * 4);
        Xsm[r * 65 + cq * 4 + 0] = v.x;
        Xsm[r * 65 + cq * 4 + 1] = v.y;
        Xsm[r * 65 + cq * 4 + 2] = v.z;
        Xsm[r * 65 + cq * 4 + 3] = v.w;
    }
    // W: 4 slices x 2 outputs x 64  (512 loads over 256 threads)
#pragma unroll
    for (int i = tid; i < 512; i += 256) {
        int p = i >> 7, o = (i >> 6) & 1, c = i & 63;
        int l = (p == 0) ? (jloc + 1) : (p == 1) ? jloc : (p == 2) ? 0 : 40;
        Wsm[p][o][c] = W[(size_t)o * (41 * 64) + l * 64 + c];
    }
    __syncthreads();

    {
        int b = tid >> 1, o = tid & 1;  // exactly 256 (b, o) pairs
        float acc0 = 0.f, acc1 = 0.f, acc2 = 0.f, acc3 = 0.f;
#pragma unroll
        for (int c = 0; c < 64; ++c) {
            float xv = Xsm[b * 65 + c];
            acc0 += xv * Wsm[0][o][c];
            acc1 += xv * Wsm[1][o][c];
            acc2 += xv * Wsm[2][o][c];
            acc3 += xv * Wsm[3][o][c];
        }
        size_t idx = ((size_t)m * BATCH + b) * 2 + o;
        g_PA[idx] = acc0; g_PB[idx] = acc1; g_PD[idx] = acc2; g_PT[idx] = acc3;
    }
}

// ---------------------------------------------------------------------------
// float4 helpers
__device__ __forceinline__ float4 f4add(float4 a, float4 b) {
    return make_float4(a.x+b.x, a.y+b.y, a.z+b.z, a.w+b.w);
}
__device__ __forceinline__ float4 f4sub(float4 a, float4 b) {
    return make_float4(a.x-b.x, a.y-b.y, a.z-b.z, a.w-b.w);
}

// Combine (vectorized, O % 4 == 0):
// out[b][f*40+ii][o] = bias + D + prefixA + (totB - incB) + T(partner), then ELU.
__global__ void k_combine4(const float* __restrict__ bias, int O, int dsel)
{
    float* out = (dsel == 0) ? g_h0 : g_h1;
    const int O4 = O >> 2;
    int t = blockIdx.x * blockDim.x + threadIdx.x;
    int total = BATCH * 2 * O4;
    if (t >= total) return;
    int og = t % O4;
    int f  = (t / O4) & 1;
    int b  = t / (2 * O4);
    int base = f * NSX;

    const float4* PA = reinterpret_cast<const float4*>(g_PA);
    const float4* PB = reinterpret_cast<const float4*>(g_PB);
    const float4* PD = reinterpret_cast<const float4*>(g_PD);
    const float4* PT = reinterpret_cast<const float4*>(g_PT);

    float4 totB = make_float4(0.f, 0.f, 0.f, 0.f);
    for (int j = 0; j < NSX; ++j)
        totB = f4add(totB, PB[((size_t)(base + j) * BATCH + b) * O4 + og]);

    float4 bv = reinterpret_cast<const float4*>(bias)[og];
    float4 accA = make_float4(0.f, 0.f, 0.f, 0.f);
    float4 accB = make_float4(0.f, 0.f, 0.f, 0.f);
    for (int ii = 0; ii < NSX; ++ii) {
        int m = base + ii;
        size_t idx = ((size_t)m * BATCH + b) * O4 + og;
        accB = f4add(accB, PB[idx]);
        int mo = (1 - f) * NSX + ii;
        float4 v = f4add(f4add(bv, PD[idx]),
                   f4add(PT[((size_t)mo * BATCH + b) * O4 + og],
                   f4add(accA, f4sub(totB, accB))));
        v.x = (v.x > 0.f) ? v.x : expm1f(v.x);
        v.y = (v.y > 0.f) ? v.y : expm1f(v.y);
        v.z = (v.z > 0.f) ? v.z : expm1f(v.z);
        v.w = (v.w > 0.f) ? v.w : expm1f(v.w);
        reinterpret_cast<float4*>(out)[((size_t)b * NKPT + m) * O4 + og] = v;
        accA = f4add(accA, PA[idx]);
    }
}

// Scalar combine for the final layer (O=2, no ELU), writes d_out.
__global__ void k_combine_final(const float* __restrict__ bias, float* __restrict__ out)
{
    const int O = 2;
    int t = blockIdx.x * blockDim.x + threadIdx.x;
    int total = BATCH * 2 * O;
    if (t >= total) return;
    int o = t % O;
    int f = (t / O) & 1;
    int b = t / (2 * O);
    int base = f * NSX;

    float totB = 0.f;
    for (int j = 0; j < NSX; ++j)
        totB += g_PB[((size_t)(base + j) * BATCH + b) * O + o];

    float accA = 0.f, accB = 0.f;
    const float bv = bias[o];
    for (int ii = 0; ii < NSX; ++ii) {
        int m = base + ii;
        size_t idx = ((size_t)m * BATCH + b) * O + o;
        accB += g_PB[idx];
        int mo = (1 - f) * NSX + ii;
        float v = bv + g_PD[idx] + g_PT[((size_t)mo * BATCH + b) * O + o]
                + accA + (totB - accB);
        out[((size_t)b * NKPT + m) * O + o] = v;
        accA += g_PA[idx];
    }
}

// ---------------------------------------------------------------------------
extern "C" void kernel_launch(void* const* d_in, const int* in_sizes, int n_in,
                              void* d_out, int out_size)
{
    const float* x  = (const float*)d_in[0];
    const float* W0 = (const float*)d_in[1];
    const float* b0 = (const float*)d_in[2];
    const float* W1 = (const float*)d_in[3];
    const float* b1 = (const float*)d_in[4];
    const float* W2 = (const float*)d_in[5];
    const float* b2 = (const float*)d_in[6];
    const float* W3 = (const float*)d_in[7];
    const float* b3 = (const float*)d_in[8];
    const float* W4 = (const float*)d_in[9];
    const float* b4 = (const float*)d_in[10];
    // d_in[11] = indices: deterministic structure hardcoded above.

    // Stage 0: x @ W0^T + b0 -> g_h0 (128 x 20480)
    k_gemm0<<<160, 256>>>(x, W0, b0);

    // Layer 1: C=256 -> O=256, ELU, g_h0 -> g_h1
    k_proj<8, 32, 256, 256><<<dim3(2, 4, 80), 256>>>(0, W1);
    k_combine4<<<(BATCH * 2 * 64 + 255) / 256, 256>>>(b1, 256, 1);

    // Layer 2: C=256 -> O=128, ELU, g_h1 -> g_h0
    k_proj<8, 32, 256, 128><<<dim3(1, 4, 80), 256>>>(1, W2);
    k_combine4<<<(BATCH * 2 * 32 + 255) / 256, 256>>>(b2, 128, 0);

    // Layer 3: C=128 -> O=64, ELU, g_h0 -> g_h1
    k_proj<4, 32, 128, 64><<<dim3(1, 4, 80), 256>>>(0, W3);
    k_combine4<<<(BATCH * 2 * 16 + 255) / 256, 256>>>(b3, 64, 1);

    // Layer 4: C=64 -> O=2, no ELU, g_h1 -> d_out
    k_proj4<<<80, 256>>>(W4);
    k_combine_final<<<(BATCH * 2 * 2 + 255) / 256, 256>>>(b4, (float*)d_out);
}

// round 4
// speedup vs baseline: 2.1351x; 2.0858x over previous
#include <cuda_runtime.h>
#include <math.h>
#include <stdint.h>

#define BATCH 128
#define NKPT  80
#define NSX   40

// ---------------- scratch (device globals; no allocation allowed) ----------
__device__ float g_h0[NKPT * 256 * BATCH];   // [m][c][b]
__device__ float g_h1[NKPT * 256 * BATCH];
__device__ float g_PA[NKPT * 256 * BATCH];   // [m][o][b]
__device__ float g_PB[NKPT * 256 * BATCH];
__device__ float g_PD[NKPT * 256 * BATCH];
__device__ float g_PT[NKPT * 256 * BATCH];
__device__ float g_W0t[1024 * 20480];        // [k][j]
__device__ float g_Wt1[10496 * 256];         // [l*256+c][o]
__device__ float g_Wt2[10496 * 128];
__device__ float g_Wt3[5248 * 64];
__device__ float g_xT [1024 * 128];          // [k][b]

// ---------------- cp.async helpers ----------------------------------------
__device__ __forceinline__ void cpa16(float* s, const float* g) {
    unsigned a = (unsigned)__cvta_generic_to_shared(s);
    asm volatile("cp.async.ca.shared.global [%0], [%1], 16;\n" :: "r"(a), "l"(g));
}
__device__ __forceinline__ void cp_commit() { asm volatile("cp.async.commit_group;\n"); }
template<int N> __device__ __forceinline__ void cp_wait() {
    asm volatile("cp.async.wait_group %0;\n" :: "n"(N));
}

// ---------------- tiled transpose: out[c][r] = in[r][c] --------------------
__global__ void k_transpose(const float* __restrict__ in, float* __restrict__ out,
                            int R, int C)
{
    __shared__ float t[32][33];
    int c0 = blockIdx.x * 32, r0 = blockIdx.y * 32;
    int tx = threadIdx.x, ty = threadIdx.y;   // 32 x 8
#pragma unroll
    for (int i = 0; i < 32; i += 8) {
        int r = r0 + ty + i, c = c0 + tx;
        if (r < R && c < C) t[ty + i][tx] = in[(size_t)r * C + c];
    }
    __syncthreads();
#pragma unroll
    for (int i = 0; i < 32; i += 8) {
        int c = c0 + ty + i, r = r0 + tx;
        if (c < C && r < R) out[(size_t)c * R + r] = t[tx][ty + i];
    }
}

// ---------------------------------------------------------------------------
// GEMM core: Out[NT o-rows x 128 b] = A[K x ldA (k-major, o contig)] *
//                                     B[K x 128 (k-major, b contig)]
// Double-buffered cp.async tiles, BKT=16. 256 threads, per-thread MR x 8.
template<int MR, int K>
__device__ __forceinline__ void gemm_core(
    const float* __restrict__ A, int ldA, int nBase0,
    const float* __restrict__ B,
    float (&acc)[MR][8], float* As, float* Bs)
{
    constexpr int NT  = 16 * MR;
    constexpr int BKT = 16;
    constexpr int nK  = K / BKT;
    const int tid   = threadIdx.x;
    const int mBase = (tid >> 4) * MR;   // o within tile
    const int nOff  = (tid & 15) * 8;    // b

#pragma unroll
    for (int i = 0; i < MR; ++i)
#pragma unroll
        for (int j = 0; j < 8; ++j) acc[i][j] = 0.f;

    auto load_tiles = [&](int it, int st) {
        const float* Ak = A + (size_t)(it * BKT) * ldA + nBase0;
        float* Asd = As + st * (BKT * NT);
#pragma unroll
        for (int i = tid; i < BKT * NT / 4; i += 256) {
            int kk = i / (NT / 4), c4 = i % (NT / 4);
            cpa16(Asd + kk * NT + c4 * 4, Ak + (size_t)kk * ldA + c4 * 4);
        }
        const float* Bk = B + (size_t)(it * BKT) * 128;
        float* Bsd = Bs + st * (BKT * 128);
#pragma unroll
        for (int i = tid; i < BKT * 128 / 4; i += 256) {
            int kk = i >> 5, b4 = i & 31;
            cpa16(Bsd + kk * 128 + b4 * 4, Bk + kk * 128 + b4 * 4);
        }
        cp_commit();
    };

    load_tiles(0, 0);
#pragma unroll 1
    for (int it = 0; it < nK; ++it) {
        if (it + 1 < nK) { load_tiles(it + 1, (it + 1) & 1); cp_wait<1>(); }
        else             { cp_wait<0>(); }
        __syncthreads();
        const float* Asd = As + (it & 1) * (BKT * NT);
        const float* Bsd = Bs + (it & 1) * (BKT * 128);
#pragma unroll
        for (int kk = 0; kk < BKT; ++kk) {
            float a[MR], bb[8];
#pragma unroll
            for (int i2 = 0; i2 < MR; i2 += 4) {
                float4 av = *reinterpret_cast<const float4*>(Asd + kk * NT + mBase + i2);
                a[i2]=av.x; a[i2+1]=av.y; a[i2+2]=av.z; a[i2+3]=av.w;
            }
            float4 b0 = *reinterpret_cast<const float4*>(Bsd + kk * 128 + nOff);
            float4 b1 = *reinterpret_cast<const float4*>(Bsd + kk * 128 + nOff + 4);
            bb[0]=b0.x; bb[1]=b0.y; bb[2]=b0.z; bb[3]=b0.w;
            bb[4]=b1.x; bb[5]=b1.y; bb[6]=b1.z; bb[7]=b1.w;
#pragma unroll
            for (int i = 0; i < MR; ++i)
#pragma unroll
                for (int j = 0; j < 8; ++j) acc[i][j] += a[i] * bb[j];
        }
        __syncthreads();
    }
}

// ---------------------------------------------------------------------------
// Stage 0: g_h0[j][b] = sum_k W0t[k][j] * xT[k][b] + b0[j]; j-tile 128.
__global__ __launch_bounds__(256, 2)
void k_gemm0(const float* __restrict__ bias)
{
    __shared__ float As[2 * 16 * 128];
    __shared__ float Bs[2 * 16 * 128];
    float acc[8][8];
    const int nBase0 = blockIdx.x * 128;
    gemm_core<8, 1024>(g_W0t, 20480, nBase0, g_xT, acc, As, Bs);

    const int tid   = threadIdx.x;
    const int mBase = (tid >> 4) * 8;
    const int nOff  = (tid & 15) * 8;
#pragma unroll
    for (int i = 0; i < 8; ++i) {
        int jrow = nBase0 + mBase + i;
        float bv = bias[jrow];
#pragma unroll
        for (int j = 0; j < 8; j += 4) {
            float4 v = make_float4(acc[i][j] + bv, acc[i][j+1] + bv,
                                   acc[i][j+2] + bv, acc[i][j+3] + bv);
            *reinterpret_cast<float4*>(&g_h0[(size_t)jrow * 128 + nOff + j]) = v;
        }
    }
}

// ---------------------------------------------------------------------------
// Projection: P_p[m][o][b] = sum_c Wt[l_p(m)*C + c][o] * h[m][c][b]
// l_p: p=0: j+1  p=1: j  p=2: 0  p=3: 40  (j = m % 40). grid (O/NT, 4, 80).
template<int MR, int C, int O>
__global__ __launch_bounds__(256, 2)
void k_proj(int ssel, int wsel)
{
    constexpr int NT = 16 * MR;
    __shared__ float As[2 * 16 * NT];
    __shared__ float Bs[2 * 16 * 128];

    const float* h  = ssel ? g_h1 : g_h0;
    const float* Wt = (wsel == 1) ? g_Wt1 : (wsel == 2) ? g_Wt2 : g_Wt3;

    const int m    = blockIdx.z;
    const int p    = blockIdx.y;
    const int jloc = m % NSX;
    const int l    = (p == 0) ? (jloc + 1) : (p == 1) ? jloc : (p == 2) ? 0 : 40;
    float* out     = (p == 0) ? g_PA : (p == 1) ? g_PB : (p == 2) ? g_PD : g_PT;

    const int nBase0 = blockIdx.x * NT;
    float acc[MR][8];
    gemm_core<MR, C>(Wt + (size_t)l * C * O, O, nBase0,
                     h + (size_t)m * C * 128, acc, As, Bs);

    const int tid   = threadIdx.x;
    const int mBase = (tid >> 4) * MR;
    const int nOff  = (tid & 15) * 8;
#pragma unroll
    for (int i = 0; i < MR; ++i) {
        int o = nBase0 + mBase + i;
#pragma unroll
        for (int j = 0; j < 8; j += 4) {
            float4 v = make_float4(acc[i][j], acc[i][j+1], acc[i][j+2], acc[i][j+3]);
            *reinterpret_cast<float4*>(
                &out[((size_t)m * O + o) * 128 + nOff + j]) = v;
        }
    }
}

// ---------------------------------------------------------------------------
// Layer 4 projection: C=64, O=2. One block per node m; all 4 p's share X.
// h layout [m][c][b] is already k-major; direct copy into smem.
__global__ __launch_bounds__(256)
void k_proj4(const float* __restrict__ W)
{
    __shared__ float Xsm[64 * 128];   // 32 KB
    __shared__ float Wsm[4][2][64];
    const int m    = blockIdx.x;
    const int jloc = m % NSX;
    const int tid  = threadIdx.x;
    const float* hs = g_h1 + (size_t)m * 64 * 128;

#pragma unroll
    for (int i = tid; i < 64 * 32; i += 256)
        reinterpret_cast<float4*>(Xsm)[i] = reinterpret_cast<const float4*>(hs)[i];
#pragma unroll
    for (int i = tid; i < 512; i += 256) {
        int p = i >> 7, o = (i >> 6) & 1, c = i & 63;
        int l = (p == 0) ? (jloc + 1) : (p == 1) ? jloc : (p == 2) ? 0 : 40;
        Wsm[p][o][c] = W[(size_t)o * (41 * 64) + l * 64 + c];
    }
    __syncthreads();

    const int b    = tid & 127;
    const int half = tid >> 7;      // half handles p = {2*half, 2*half+1}
    float a00 = 0.f, a01 = 0.f, a10 = 0.f, a11 = 0.f;
#pragma unroll
    for (int c = 0; c < 64; ++c) {
        float xv = Xsm[c * 128 + b];
        a00 += xv * Wsm[2 * half + 0][0][c];
        a01 += xv * Wsm[2 * half + 0][1][c];
        a10 += xv * Wsm[2 * half + 1][0][c];
        a11 += xv * Wsm[2 * half + 1][1][c];
    }
    float* o0 = half ? g_PD : g_PA;
    float* o1 = half ? g_PT : g_PB;
    o0[((size_t)m * 2 + 0) * 128 + b] = a00;
    o0[((size_t)m * 2 + 1) * 128 + b] = a01;
    o1[((size_t)m * 2 + 0) * 128 + b] = a10;
    o1[((size_t)m * 2 + 1) * 128 + b] = a11;
}

// ---------------------------------------------------------------------------
// Combine: out[(m*O+o)*128+b] = ELU(bias + D + prefixA + (totB - incB) + T(partner))
// Thread per (b, f, o); b fastest -> fully coalesced.
__global__ void k_comb(const float* __restrict__ bias, int O, int dsel)
{
    float* out = dsel ? g_h1 : g_h0;
    int t = blockIdx.x * blockDim.x + threadIdx.x;
    if (t >= BATCH * 2 * O) return;
    int b = t & 127;
    int rest = t >> 7;
    int f = rest & 1;
    int o = rest >> 1;
    int base = f * NSX;

    float totB = 0.f;
    for (int j = 0; j < NSX; ++j)
        totB += g_PB[((size_t)(base + j) * O + o) * 128 + b];

    float accA = 0.f, accB = 0.f;
    const float bv = bias[o];
    for (int ii = 0; ii < NSX; ++ii) {
        int m = base + ii;
        size_t idx = ((size_t)m * O + o) * 128 + b;
        accB += g_PB[idx];
        int mo = (1 - f) * NSX + ii;
        float v = bv + g_PD[idx] + g_PT[((size_t)mo * O + o) * 128 + b]
                + accA + (totB - accB);
        v = (v > 0.f) ? v : expm1f(v);
        out[idx] = v;
        accA += g_PA[idx];
    }
}

// Final combine: O=2, no ELU, write d_out[b][m][o].
__global__ void k_comb_final(const float* __restrict__ bias, float* __restrict__ out)
{
    const int O = 2;
    int t = blockIdx.x * blockDim.x + threadIdx.x;
    if (t >= BATCH * 2 * O) return;
    int b = t & 127;
    int rest = t >> 7;
    int f = rest & 1;
    int o = rest >> 1;
    int base = f * NSX;

    float totB = 0.f;
    for (int j = 0; j < NSX; ++j)
        totB += g_PB[((size_t)(base + j) * O + o) * 128 + b];

    float accA = 0.f, accB = 0.f;
    const float bv = bias[o];
    for (int ii = 0; ii < NSX; ++ii) {
        int m = base + ii;
        size_t idx = ((size_t)m * O + o) * 128 + b;
        accB += g_PB[idx];
        int mo = (1 - f) * NSX + ii;
        float v = bv + g_PD[idx] + g_PT[((size_t)mo * O + o) * 128 + b]
                + accA + (totB - accB);
        out[((size_t)b * NKPT + m) * 2 + o] = v;
        accA += g_PA[idx];
    }
}

// ---------------------------------------------------------------------------
extern "C" void kernel_launch(void* const* d_in, const int* in_sizes, int n_in,
                              void* d_out, int out_size)
{
    (void)in_sizes; (void)n_in; (void)out_size;
    const float* x  = (const float*)d_in[0];
    const float* W0 = (const float*)d_in[1];
    const float* b0 = (const float*)d_in[2];
    const float* W1 = (const float*)d_in[3];
    const float* b1 = (const float*)d_in[4];
    const float* W2 = (const float*)d_in[5];
    const float* b2 = (const float*)d_in[6];
    const float* W3 = (const float*)d_in[7];
    const float* b3 = (const float*)d_in[8];
    const float* W4 = (const float*)d_in[9];
    const float* b4 = (const float*)d_in[10];
    // d_in[11] = indices: deterministic structure hardcoded above.

    dim3 tt(32, 8);
    // Pre-transposes (k-major operands)
    float* pW0t; cudaGetSymbolAddress((void**)&pW0t, g_W0t);
    float* pWt1; cudaGetSymbolAddress((void**)&pWt1, g_Wt1);
    float* pWt2; cudaGetSymbolAddress((void**)&pWt2, g_Wt2);
    float* pWt3; cudaGetSymbolAddress((void**)&pWt3, g_Wt3);
    float* pxT;  cudaGetSymbolAddress((void**)&pxT,  g_xT);

    k_transpose<<<dim3(1024 / 32, 20480 / 32), tt>>>(W0, pW0t, 20480, 1024);
    k_transpose<<<dim3(1024 / 32, 128 / 32),   tt>>>(x,  pxT,  128,   1024);
    k_transpose<<<dim3(10496 / 32, 256 / 32),  tt>>>(W1, pWt1, 256,  10496);
    k_transpose<<<dim3(10496 / 32, 128 / 32),  tt>>>(W2, pWt2, 128,  10496);
    k_transpose<<<dim3(5248 / 32, 64 / 32),    tt>>>(W3, pWt3, 64,   5248);

    // Stage 0: W0t^T-free GEMM -> g_h0 [m][c][b]
    k_gemm0<<<160, 256>>>(b0);

    // Layer 1: C=256 -> O=256, ELU, g_h0 -> g_h1
    k_proj<8, 256, 256><<<dim3(2, 4, 80), 256>>>(0, 1);
    k_comb<<<(BATCH * 2 * 256 + 255) / 256, 256>>>(b1, 256, 1);

    // Layer 2: C=256 -> O=128, ELU, g_h1 -> g_h0
    k_proj<8, 256, 128><<<dim3(1, 4, 80), 256>>>(1, 2);
    k_comb<<<(BATCH * 2 * 128 + 255) / 256, 256>>>(b2, 128, 0);

    // Layer 3: C=128 -> O=64, ELU, g_h0 -> g_h1
    k_proj<4, 128, 64><<<dim3(1, 4, 80), 256>>>(0, 3);
    k_comb<<<(BATCH * 2 * 64 + 255) / 256, 256>>>(b3, 64, 1);

    // Layer 4: C=64 -> O=2, no ELU, g_h1 -> d_out
    k_proj4<<<80, 256>>>(W4);
    k_comb_final<<<2, 256>>>(b4, (float*)d_out);
}